// round 3
// baseline (speedup 1.0000x reference)
#include <cuda_runtime.h>
#include <math.h>

#define N_ 20000
#define E_ 320000
#define G_ 128
#define H_ 64
#define L_ 4
#define AVG_D_LOG 2.8332133440562162f  /* log(17.0) */

typedef unsigned long long ull;

/* ------------------------------------------------------------------ */
/* Scratch                                                             */
/* ------------------------------------------------------------------ */
__device__ int   g_degi[N_];
__device__ float g_amp[N_], g_att[N_];
__device__ int   g_rowoff[N_ + 1];
__device__ int   g_cursor[N_];
__device__ int   g_psrc[E_], g_pdst[E_];
__device__ float g_x[N_ * H_];
__device__ float g_m[E_ * H_];
__device__ float g_agg[N_ * 4 * H_];
__device__ float g_gsum[G_ * H_];
__device__ float g_gcnt[G_];

/* ------------------------------------------------------------------ */
/* Packed f32x2 helpers                                                */
/* ------------------------------------------------------------------ */
__device__ __forceinline__ ull pk2(float x, float y)
{
    ull r;
    asm("mov.b64 %0, {%1,%2};" : "=l"(r) : "f"(x), "f"(y));
    return r;
}
__device__ __forceinline__ void fma2(ull& d, ull a, ull b)
{
    asm("fma.rn.f32x2 %0, %1, %2, %0;" : "+l"(d) : "l"(a), "l"(b));
}
__device__ __forceinline__ void upk2(ull v, float& x, float& y)
{
    asm("mov.b64 {%0,%1}, %2;" : "=f"(x), "=f"(y) : "l"(v));
}

/* ------------------------------------------------------------------ */
/* Setup                                                               */
/* ------------------------------------------------------------------ */
__global__ void k_zero()
{
    int i = blockIdx.x * blockDim.x + threadIdx.x;
    if (i < N_)       g_degi[i] = 0;
    if (i < G_)       g_gcnt[i] = 0.f;
    if (i < G_ * H_)  g_gsum[i] = 0.f;
}

__global__ void k_count(const int* __restrict__ dst)
{
    int e = blockIdx.x * blockDim.x + threadIdx.x;
    if (e < E_) atomicAdd(&g_degi[dst[e]], 1);
}

__global__ void k_gcnt(const int* __restrict__ gid)
{
    int n = blockIdx.x * blockDim.x + threadIdx.x;
    if (n < N_) atomicAdd(&g_gcnt[gid[n]], 1.0f);
}

/* block scan + scalers + cursor init, fused                           */
__global__ void k_scan()
{
    int t  = threadIdx.x;
    int i0 = t * 20;
    int loc[20], val[20];
    int s = 0;
#pragma unroll
    for (int k = 0; k < 20; k++) {
        int i = i0 + k;
        int v = (i < N_) ? g_degi[i] : 0;
        loc[k] = s;
        val[k] = v;
        s += v;
    }
    int lane = t & 31, w = t >> 5;
    int x = s;
#pragma unroll
    for (int off = 1; off < 32; off <<= 1) {
        int y = __shfl_up_sync(0xffffffffu, x, off);
        if (lane >= off) x += y;
    }
    __shared__ int wsum[32];
    if (lane == 31) wsum[w] = x;
    __syncthreads();
    if (w == 0) {
        int y = wsum[lane];
#pragma unroll
        for (int off = 1; off < 32; off <<= 1) {
            int z = __shfl_up_sync(0xffffffffu, y, off);
            if (lane >= off) y += z;
        }
        wsum[lane] = y;
    }
    __syncthreads();
    int base = x - s + ((w > 0) ? wsum[w - 1] : 0);
#pragma unroll
    for (int k = 0; k < 20; k++) {
        int i = i0 + k;
        if (i < N_) {
            int off = base + loc[k];
            g_rowoff[i] = off;
            g_cursor[i] = off;
            float d    = (float)val[k];
            float logd = logf(d + 1.0f);
            g_amp[i] = logd / AVG_D_LOG;
            g_att[i] = AVG_D_LOG / fmaxf(logd, 1e-5f);
        } else if (i == N_) {
            g_rowoff[i] = base + loc[k];
        }
    }
    if (t == 1023) g_rowoff[N_] = base + s;  /* N_=20000 < 20480: covered above too */
}

__global__ void k_scatter(const int* __restrict__ src, const int* __restrict__ dst)
{
    int e = blockIdx.x * blockDim.x + threadIdx.x;
    if (e >= E_) return;
    int d = dst[e];
    int p = atomicAdd(&g_cursor[d], 1);
    g_psrc[p] = src[e];
    g_pdst[p] = d;
}

/* ------------------------------------------------------------------ */
/* Embedding                                                           */
/* ------------------------------------------------------------------ */
__global__ void k_embed(const float* __restrict__ h,
                        const float* __restrict__ embW,
                        const float* __restrict__ embB)
{
    int id = blockIdx.x * blockDim.x + threadIdx.x;
    if (id >= N_ * H_) return;
    int n = id >> 6, c = id & 63;
    const float* hr = h + n * 16;
    float a = embB[c];
#pragma unroll
    for (int k = 0; k < 16; k++)
        a = fmaf(hr[k], embW[k * H_ + c], a);
    g_x[id] = a;
}

/* ------------------------------------------------------------------ */
/* Edge pretrans GEMM: BM=128 edges, BN=64, K=128 (4 subtiles of 32).  */
/* 128 threads, 8x8 micro-tile, M-pair FFMA2, B pre-duplicated.        */
/* ------------------------------------------------------------------ */
__global__ void __launch_bounds__(128, 4)
k_edge(const float* __restrict__ preW, const float* __restrict__ preB)
{
    __shared__ float sA[32][130];        /* [k][edge], stride even for LDS.64  */
    __shared__ ull   sBd[32][65];        /* dup pairs, [k][col]                */
    __shared__ int   sIdx[2][128];

    int t  = threadIdx.x;
    int e0 = blockIdx.x * 128;
    int tx = t & 7, ty = t >> 3;

    sIdx[0][t] = g_psrc[e0 + t];
    sIdx[1][t] = g_pdst[e0 + t];

    ull acc[4][8];
#pragma unroll
    for (int j = 0; j < 8; j++) {
        float b = preB[j * 8 + tx];
        ull bb = pk2(b, b);
#pragma unroll
        for (int mp = 0; mp < 4; mp++) acc[mp][j] = bb;
    }
    __syncthreads();

#pragma unroll
    for (int half = 0; half < 2; half++) {
#pragma unroll
        for (int ks = 0; ks < 2; ks++) {
            /* B subtile -> duplicated pairs */
#pragma unroll
            for (int r = 0; r < 4; r++) {
                int li = t + 128 * r;
                int kl = li >> 4, c4 = li & 15;
                float4 wv = *(const float4*)(preW + (half * 64 + ks * 32 + kl) * 64 + c4 * 4);
                sBd[kl][c4 * 4 + 0] = pk2(wv.x, wv.x);
                sBd[kl][c4 * 4 + 1] = pk2(wv.y, wv.y);
                sBd[kl][c4 * 4 + 2] = pk2(wv.z, wv.z);
                sBd[kl][c4 * 4 + 3] = pk2(wv.w, wv.w);
            }
            /* A subtile gather (transposed) */
#pragma unroll
            for (int r = 0; r < 8; r++) {
                int li = t + 128 * r;
                int e = li >> 3, c4 = li & 7;
                int nd = sIdx[half][e];
                float4 v = *(const float4*)(g_x + nd * 64 + ks * 32 + c4 * 4);
                sA[c4 * 4 + 0][e] = v.x;
                sA[c4 * 4 + 1][e] = v.y;
                sA[c4 * 4 + 2][e] = v.z;
                sA[c4 * 4 + 3][e] = v.w;
            }
            __syncthreads();
#pragma unroll 2
            for (int kk = 0; kk < 32; kk++) {
                ull B[8], A[4];
#pragma unroll
                for (int j = 0; j < 8; j++)  B[j]  = sBd[kk][j * 8 + tx];
#pragma unroll
                for (int mp = 0; mp < 4; mp++) A[mp] = *(const ull*)&sA[kk][ty * 8 + 2 * mp];
#pragma unroll
                for (int mp = 0; mp < 4; mp++)
#pragma unroll
                    for (int j = 0; j < 8; j++)
                        fma2(acc[mp][j], A[mp], B[j]);
            }
            __syncthreads();
        }
    }

    /* epilogue: rows e0+ty*8+2mp(+1), cols j*8+tx */
#pragma unroll
    for (int mp = 0; mp < 4; mp++) {
        int p0 = e0 + ty * 8 + 2 * mp;
        float* o0 = g_m + (size_t)p0 * 64;
        float* o1 = o0 + 64;
#pragma unroll
        for (int j = 0; j < 8; j++) {
            float lo, hi;
            upk2(acc[mp][j], lo, hi);
            o0[j * 8 + tx] = lo;
            o1[j * 8 + tx] = hi;
        }
    }
}

/* ------------------------------------------------------------------ */
/* Aggregate: warp per node, CSR walk -> mean/max/min/std              */
/* ------------------------------------------------------------------ */
__global__ void k_agg()
{
    int gw   = (blockIdx.x * blockDim.x + threadIdx.x) >> 5;
    int lane = threadIdx.x & 31;
    if (gw >= N_) return;

    int r0 = g_rowoff[gw], r1 = g_rowoff[gw + 1];
    float sx = 0.f, sy = 0.f, qx = 0.f, qy = 0.f;
    float mxx = -INFINITY, mxy = -INFINITY;
    float mnx =  INFINITY, mny =  INFINITY;

    const float2* M = (const float2*)g_m;
    for (int p = r0; p < r1; p++) {
        float2 v = M[p * 32 + lane];
        sx += v.x; sy += v.y;
        qx = fmaf(v.x, v.x, qx); qy = fmaf(v.y, v.y, qy);
        mxx = fmaxf(mxx, v.x); mxy = fmaxf(mxy, v.y);
        mnx = fminf(mnx, v.x); mny = fminf(mny, v.y);
    }
    int   deg  = r1 - r0;
    float degc = fmaxf((float)deg, 1.0f);
    float meanx = sx / degc, meany = sy / degc;
    float msqx  = qx / degc, msqy  = qy / degc;
    float stdx = sqrtf(fmaxf(msqx - meanx * meanx, 0.f) + 1e-5f);
    float stdy = sqrtf(fmaxf(msqy - meany * meany, 0.f) + 1e-5f);
    if (deg == 0) { mxx = mxy = 0.f; mnx = mny = 0.f; }

    float2* A = (float2*)(g_agg + gw * (4 * H_));
    A[lane]      = make_float2(meanx, meany);
    A[32 + lane] = make_float2(mxx, mxy);
    A[64 + lane] = make_float2(mnx, mny);
    A[96 + lane] = make_float2(stdx, stdy);
}

/* ------------------------------------------------------------------ */
/* Fused posttrans + mixing:                                           */
/* stage1: y = A'[64n,832] @ postW + postB  (A' on the fly)            */
/* stage2: x += leaky(y @ mixW + mixB) * snorm                         */
/* ------------------------------------------------------------------ */
__global__ void __launch_bounds__(256, 2)
k_postmix(const float* __restrict__ postW, const float* __restrict__ postB,
          const float* __restrict__ mixW,  const float* __restrict__ mixB,
          const float* __restrict__ snorm)
{
    __shared__ float sY[64][66];                 /* y transposed: [k][node]    */
    __shared__ float sAmp[64], sAtt[64];
    __shared__ __align__(16) unsigned char uBuf[32 * 66 * 4 + 32 * 65 * 8];
    float (*sA)[66]  = (float(*)[66])uBuf;
    ull   (*sBd)[65] = (ull(*)[65])(uBuf + 32 * 66 * 4);
    float (*sW)[68]  = (float(*)[68])uBuf;       /* stage2 reuse */

    int t  = threadIdx.x;
    int n0 = blockIdx.x * 64;
    int tx = t & 15, ty = t >> 4;

    if (t < 64) {
        int n = n0 + t;
        sAmp[t] = (n < N_) ? g_amp[n] : 0.f;
        sAtt[t] = (n < N_) ? g_att[n] : 0.f;
    }
    __syncthreads();

    /* ---------------- stage 1: posttrans ---------------- */
    ull acc[2][4];
#pragma unroll
    for (int j = 0; j < 4; j++) {
        float b = postB[j * 16 + tx];
        ull bb = pk2(b, b);
        acc[0][j] = bb; acc[1][j] = bb;
    }

    for (int kt = 0; kt < 26; kt++) {
#pragma unroll
        for (int r = 0; r < 2; r++) {
            int li = t + 256 * r;
            int kl = li >> 4, c4 = li & 15;
            float4 wv = *(const float4*)(postW + (kt * 32 + kl) * 64 + c4 * 4);
            sBd[kl][c4 * 4 + 0] = pk2(wv.x, wv.x);
            sBd[kl][c4 * 4 + 1] = pk2(wv.y, wv.y);
            sBd[kl][c4 * 4 + 2] = pk2(wv.z, wv.z);
            sBd[kl][c4 * 4 + 3] = pk2(wv.w, wv.w);
        }
#pragma unroll
        for (int r = 0; r < 8; r++) {
            int li = t + 256 * r;
            int nl = li >> 5, kl = li & 31;
            int n  = n0 + nl;
            float v = 0.f;
            if (n < N_) {
                if (kt < 8)       v = g_agg[n * 256 + kt * 32 + kl];
                else if (kt < 16) v = g_agg[n * 256 + (kt - 8)  * 32 + kl] * sAmp[nl];
                else if (kt < 24) v = g_agg[n * 256 + (kt - 16) * 32 + kl] * sAtt[nl];
                else              v = g_x[n * 64 + (kt - 24) * 32 + kl];
            }
            sA[kl][nl] = v;
        }
        __syncthreads();
#pragma unroll 4
        for (int kk = 0; kk < 32; kk++) {
            ull A0 = *(const ull*)&sA[kk][ty * 4 + 0];
            ull A1 = *(const ull*)&sA[kk][ty * 4 + 2];
#pragma unroll
            for (int j = 0; j < 4; j++) {
                ull B = sBd[kk][j * 16 + tx];
                fma2(acc[0][j], A0, B);
                fma2(acc[1][j], A1, B);
            }
        }
        __syncthreads();
    }

    /* y -> sY transposed [k][node] */
#pragma unroll
    for (int i2 = 0; i2 < 2; i2++) {
        int r = ty * 4 + 2 * i2;
#pragma unroll
        for (int j = 0; j < 4; j++) {
            float lo, hi;
            upk2(acc[i2][j], lo, hi);
            sY[j * 16 + tx][r]     = lo;
            sY[j * 16 + tx][r + 1] = hi;
        }
    }
    __syncthreads();

    /* ---------------- stage 2: mixing ---------------- */
#pragma unroll
    for (int r = 0; r < 4; r++) {
        int li = t + 256 * r;
        int kl = li >> 4, c4 = li & 15;
        *(float4*)&sW[kl][c4 * 4] = *(const float4*)(mixW + kl * 64 + c4 * 4);
    }
    ull macc[2][4];
#pragma unroll
    for (int j = 0; j < 4; j++) {
        float b = mixB[tx * 4 + j];
        ull bb = pk2(b, b);
        macc[0][j] = bb; macc[1][j] = bb;
    }
    __syncthreads();

#pragma unroll 4
    for (int kk = 0; kk < 64; kk++) {
        ull A0 = *(const ull*)&sY[kk][ty * 4 + 0];
        ull A1 = *(const ull*)&sY[kk][ty * 4 + 2];
        float4 b = *(const float4*)&sW[kk][tx * 4];
        ull B0 = pk2(b.x, b.x), B1 = pk2(b.y, b.y);
        ull B2 = pk2(b.z, b.z), B3 = pk2(b.w, b.w);
        fma2(macc[0][0], A0, B0); fma2(macc[0][1], A0, B1);
        fma2(macc[0][2], A0, B2); fma2(macc[0][3], A0, B3);
        fma2(macc[1][0], A1, B0); fma2(macc[1][1], A1, B1);
        fma2(macc[1][2], A1, B2); fma2(macc[1][3], A1, B3);
    }

    /* epilogue: leaky + snorm + residual */
#pragma unroll
    for (int i2 = 0; i2 < 2; i2++) {
        float v0[4], v1[4];
#pragma unroll
        for (int j = 0; j < 4; j++) upk2(macc[i2][j], v0[j], v1[j]);
        int r = ty * 4 + 2 * i2;
#pragma unroll
        for (int hfl = 0; hfl < 2; hfl++) {
            int n = n0 + r + hfl;
            if (n >= N_) continue;
            float sn = snorm[n];
            float* xp = g_x + n * 64 + tx * 4;
            float4 cur = *(float4*)xp;
            float* vv = hfl ? v1 : v0;
            float u0 = vv[0]; u0 = (u0 > 0.f) ? u0 : 0.01f * u0;
            float u1 = vv[1]; u1 = (u1 > 0.f) ? u1 : 0.01f * u1;
            float u2 = vv[2]; u2 = (u2 > 0.f) ? u2 : 0.01f * u2;
            float u3 = vv[3]; u3 = (u3 > 0.f) ? u3 : 0.01f * u3;
            cur.x += u0 * sn; cur.y += u1 * sn;
            cur.z += u2 * sn; cur.w += u3 * sn;
            *(float4*)xp = cur;
        }
    }
}

/* ------------------------------------------------------------------ */
/* Readout                                                             */
/* ------------------------------------------------------------------ */
__global__ void k_gaccum(const int* __restrict__ gid)
{
    int id = blockIdx.x * blockDim.x + threadIdx.x;
    if (id >= N_ * H_) return;
    int n = id >> 6, c = id & 63;
    atomicAdd(&g_gsum[gid[n] * 64 + c], g_x[id]);
}

__global__ void k_final(const float* __restrict__ r1W, const float* __restrict__ r1B,
                        const float* __restrict__ r2W, const float* __restrict__ r2B,
                        const float* __restrict__ r3W, const float* __restrict__ r3B,
                        float* __restrict__ out)
{
    int g = threadIdx.x;
    if (g >= G_) return;
    float cnt = fmaxf(g_gcnt[g], 1.0f);
    float hg[64];
#pragma unroll
    for (int k = 0; k < 64; k++) hg[k] = g_gsum[g * 64 + k] / cnt;

    float t1[32];
#pragma unroll
    for (int j = 0; j < 32; j++) {
        float a = r1B[j];
        for (int k = 0; k < 64; k++) a = fmaf(hg[k], r1W[k * 32 + j], a);
        t1[j] = fmaxf(a, 0.f);
    }
    float t2[16];
#pragma unroll
    for (int j = 0; j < 16; j++) {
        float a = r2B[j];
        for (int k = 0; k < 32; k++) a = fmaf(t1[k], r2W[k * 16 + j], a);
        t2[j] = fmaxf(a, 0.f);
    }
#pragma unroll
    for (int c = 0; c < 10; c++) {
        float a = r3B[c];
        for (int k = 0; k < 16; k++) a = fmaf(t2[k], r3W[k * 10 + c], a);
        out[g * 10 + c] = a;
    }
}

/* ------------------------------------------------------------------ */
/* Host launch                                                         */
/* ------------------------------------------------------------------ */
extern "C" void kernel_launch(void* const* d_in, const int* in_sizes, int n_in,
                              void* d_out, int out_size)
{
    const float* h      = (const float*)d_in[0];
    const float* snorm  = (const float*)d_in[1];
    const float* embW   = (const float*)d_in[2];
    const float* embB   = (const float*)d_in[3];
    const float* preW   = (const float*)d_in[4];
    const float* preB   = (const float*)d_in[5];
    const float* postW  = (const float*)d_in[6];
    const float* postB  = (const float*)d_in[7];
    const float* mixW   = (const float*)d_in[8];
    const float* mixB   = (const float*)d_in[9];
    const float* r1W    = (const float*)d_in[10];
    const float* r1B    = (const float*)d_in[11];
    const float* r2W    = (const float*)d_in[12];
    const float* r2B    = (const float*)d_in[13];
    const float* r3W    = (const float*)d_in[14];
    const float* r3B    = (const float*)d_in[15];
    const int*   src    = (const int*)d_in[16];
    const int*   dst    = (const int*)d_in[17];
    const int*   gid    = (const int*)d_in[18];
    float* out = (float*)d_out;

    k_zero   <<<(N_ + 255) / 256, 256>>>();
    k_count  <<<(E_ + 255) / 256, 256>>>(dst);
    k_gcnt   <<<(N_ + 255) / 256, 256>>>(gid);
    k_scan   <<<1, 1024>>>();
    k_scatter<<<(E_ + 255) / 256, 256>>>(src, dst);

    k_embed<<<(N_ * H_ + 255) / 256, 256>>>(h, embW, embB);

    for (int i = 0; i < L_; i++) {
        k_edge   <<<E_ / 128, 128>>>(preW + i * 128 * 64, preB + i * 64);
        k_agg    <<<(N_ * 32 + 255) / 256, 256>>>();
        k_postmix<<<(N_ + 63) / 64, 256>>>(postW + i * 832 * 64, postB + i * 64,
                                           mixW + i * 64 * 64, mixB + i * 64, snorm);
    }

    k_gaccum<<<(N_ * H_ + 255) / 256, 256>>>(gid);
    k_final <<<1, 128>>>(r1W, r1B, r2W, r2B, r3W, r3B, out);
}